// round 6
// baseline (speedup 1.0000x reference)
#include <cuda_runtime.h>
#include <math.h>

#define N_NODES 100000
#define IN_DIM 256
#define HID 64
#define HEADS 3
#define FDIM 192          // HEADS*HID
#define NUM_CLASSES 10
#define NUM_GRAPHS 64
#define MAX_ET 1700000    // 1.6M edges + 100k self loops

// ---------------- static scratch (no allocations allowed) ----------------
__device__ float g_xl[(size_t)N_NODES * FDIM];
__device__ float g_xr[(size_t)N_NODES * FDIM];
__device__ int   g_src[MAX_ET];
__device__ int   g_deg[N_NODES];
__device__ int   g_tmp[N_NODES];
__device__ int   g_off[N_NODES + 1];
__device__ int   g_cur[N_NODES];
__device__ int   g_bsum[128];
__device__ float g_gsum[NUM_GRAPHS * FDIM];
__device__ int   g_gcnt[NUM_GRAPHS];

// ---------------- init ----------------
__global__ void k_zero() {
    int i = blockIdx.x * blockDim.x + threadIdx.x;
    if (i < N_NODES) g_deg[i] = 0;
    if (i < NUM_GRAPHS * FDIM) g_gsum[i] = 0.f;
    if (i < NUM_GRAPHS) g_gcnt[i] = 0;
}

// packed fp32x2 helpers (B300: FFMA2 only reachable via PTX fma.rn.f32x2,
// runs at 2x the 3-register FFMA rate)
__device__ __forceinline__ void fma_f32x2(unsigned long long& d,
                                          unsigned long long a,
                                          unsigned long long b) {
    asm("fma.rn.f32x2 %0, %1, %2, %0;" : "+l"(d) : "l"(a), "l"(b));
}
__device__ __forceinline__ unsigned long long dup_f32x2(float v) {
    unsigned long long r;
    asm("mov.b64 %0, {%1, %1};" : "=l"(r) : "r"(__float_as_uint(v)));
    return r;
}

// ---------------- fused GEMM: [xl | xr] = x @ [W_l | W_r] + [b_l | b_r] ----
// M=100000, K=256, Ncols=384. 128x128x8 tiles, 256 threads, 8x8 per thread.
// Inner product uses packed f32x2 FMA (FFMA2) -> 2x fp32 pipe throughput.
__global__ __launch_bounds__(256) void k_gemm(
    const float* __restrict__ x,
    const float* __restrict__ Wl, const float* __restrict__ Wr,
    const float* __restrict__ bl, const float* __restrict__ br)
{
    __shared__ float As[8][132];
    __shared__ float Bs[8][128];
    const int tid = threadIdx.x;
    const int tx = tid & 15;          // 0..15 (cols)
    const int ty = tid >> 4;          // 0..15 (rows)
    const int row0 = blockIdx.y * 128;
    const int col0 = blockIdx.x * 128;

    // acc2[i][j] holds columns (2j, 2j+1) for row i, packed f32x2
    unsigned long long acc2[8][4];
#pragma unroll
    for (int i = 0; i < 8; i++)
#pragma unroll
        for (int j = 0; j < 4; j++) acc2[i][j] = 0ull;   // {+0.f, +0.f}

    const int ar = tid >> 1;          // 0..127
    const int ac = (tid & 1) * 4;     // 0 or 4
    const int bk = tid >> 5;          // 0..7
    const int bn = (tid & 31) * 4;    // 0..124
    const int gcol = col0 + bn;
    const float* Wp;
    int wc;
    if (gcol < FDIM) { Wp = Wl; wc = gcol; } else { Wp = Wr; wc = gcol - FDIM; }

    for (int kt = 0; kt < IN_DIM; kt += 8) {
        // A tile (128x8), transposed into As[k][m]
        float4 av = make_float4(0.f, 0.f, 0.f, 0.f);
        int grow = row0 + ar;
        if (grow < N_NODES)
            av = *(const float4*)&x[(size_t)grow * IN_DIM + kt + ac];
        As[ac + 0][ar] = av.x;
        As[ac + 1][ar] = av.y;
        As[ac + 2][ar] = av.z;
        As[ac + 3][ar] = av.w;
        // B tile (8x128)
        float4 bv = *(const float4*)&Wp[(size_t)(kt + bk) * FDIM + wc];
        *(float4*)&Bs[bk][bn] = bv;
        __syncthreads();
#pragma unroll
        for (int k = 0; k < 8; k++) {
            // b pairs: 4 aligned 8-byte loads (tx*8 is even -> 8B aligned)
            unsigned long long bb[4];
#pragma unroll
            for (int j = 0; j < 4; j++)
                bb[j] = *(const unsigned long long*)&Bs[k][tx * 8 + 2 * j];
            float a_s[8];
#pragma unroll
            for (int i = 0; i < 8; i++) a_s[i] = As[k][ty * 8 + i];
#pragma unroll
            for (int i = 0; i < 8; i++) {
                unsigned long long aa = dup_f32x2(a_s[i]);
#pragma unroll
                for (int j = 0; j < 4; j++) fma_f32x2(acc2[i][j], aa, bb[j]);
            }
        }
        __syncthreads();
    }
#pragma unroll
    for (int i = 0; i < 8; i++) {
        int r = row0 + ty * 8 + i;
        if (r >= N_NODES) continue;
#pragma unroll
        for (int j = 0; j < 4; j++) {
            unsigned int lo, hi;
            asm("mov.b64 {%0, %1}, %2;" : "=r"(lo), "=r"(hi) : "l"(acc2[i][j]));
            float v0 = __uint_as_float(lo);
            float v1 = __uint_as_float(hi);
            int c0 = col0 + tx * 8 + 2 * j;
            int c1 = c0 + 1;
            if (c0 < FDIM) g_xl[(size_t)r * FDIM + c0] = v0 + bl[c0];
            else           g_xr[(size_t)r * FDIM + (c0 - FDIM)] = v0 + br[c0 - FDIM];
            if (c1 < FDIM) g_xl[(size_t)r * FDIM + c1] = v1 + bl[c1];
            else           g_xr[(size_t)r * FDIM + (c1 - FDIM)] = v1 + br[c1 - FDIM];
        }
    }
}

// ---------------- CSR build (edge_index is INT32: jax x64 is disabled) ----
__global__ void k_deg(const int* __restrict__ eidx, int E, int ET) {
    int e = blockIdx.x * blockDim.x + threadIdx.x;
    if (e >= ET) return;
    int dst = (e < E) ? eidx[(size_t)E + e] : (e - E);
    if ((unsigned)dst >= N_NODES) return;   // defensive: wrong dtype -> rel_err, not trap
    atomicAdd(&g_deg[dst], 1);
}

__global__ void k_scan1() {   // 98 blocks x 1024: per-chunk inclusive scan
    __shared__ int s[1024];
    int tid = threadIdx.x;
    int i = blockIdx.x * 1024 + tid;
    int v = (i < N_NODES) ? g_deg[i] : 0;
    s[tid] = v;
    __syncthreads();
#pragma unroll
    for (int o = 1; o < 1024; o <<= 1) {
        int t = (tid >= o) ? s[tid - o] : 0;
        __syncthreads();
        s[tid] += t;
        __syncthreads();
    }
    if (i < N_NODES) g_tmp[i] = s[tid];
    if (tid == 1023) g_bsum[blockIdx.x] = s[1023];
}

__global__ void k_scan2(int nblk) {  // serial exclusive scan of block sums
    if (threadIdx.x == 0 && blockIdx.x == 0) {
        int run = 0;
        for (int b = 0; b < nblk; b++) { int t = g_bsum[b]; g_bsum[b] = run; run += t; }
    }
}

__global__ void k_scan3() {
    int i = blockIdx.x * blockDim.x + threadIdx.x;
    if (i >= N_NODES) return;
    int val = g_tmp[i] + g_bsum[i >> 10];
    g_off[i + 1] = val;
    g_cur[i] = val - g_deg[i];
    if (i == 0) g_off[0] = 0;
}

__global__ void k_fill(const int* __restrict__ eidx, int E, int ET) {
    int e = blockIdx.x * blockDim.x + threadIdx.x;
    if (e >= ET) return;
    int src, dst;
    if (e < E) { src = eidx[e]; dst = eidx[(size_t)E + e]; }
    else       { src = e - E; dst = e - E; }
    if ((unsigned)dst >= N_NODES || (unsigned)src >= N_NODES) return;  // defensive
    int p = atomicAdd(&g_cur[dst], 1);
    if ((unsigned)p < MAX_ET) g_src[p] = src;
}

// ---------------- warp-per-node GATv2 with online softmax ----------------
__global__ __launch_bounds__(256) void k_attn(
    const float* __restrict__ att, const float* __restrict__ bias,
    float* __restrict__ out_fc, float* __restrict__ out_pre)
{
    int warp = (blockIdx.x * blockDim.x + threadIdx.x) >> 5;
    int lane = threadIdx.x & 31;
    if (warp >= N_NODES) return;
    const int i = warp;

    float xrv[6], attv[6];
#pragma unroll
    for (int k = 0; k < 6; k++) {
        int c = lane + 32 * k;
        xrv[k] = g_xr[(size_t)i * FDIM + c];
        attv[k] = att[c];   // att flattened [3,64] == channel index
    }
    int beg = g_off[i], end = g_off[i + 1];

    float m0 = -1e30f, m1 = -1e30f, m2 = -1e30f;
    float d0 = 0.f, d1 = 0.f, d2 = 0.f;
    float acc[6] = {0.f, 0.f, 0.f, 0.f, 0.f, 0.f};

    for (int e = beg; e < end; e++) {
        int s = g_src[e];
        const float* xl = &g_xl[(size_t)s * FDIM];
        float xlv[6];
        float p0 = 0.f, p1 = 0.f, p2 = 0.f;
#pragma unroll
        for (int k = 0; k < 6; k++) {
            float v = xl[lane + 32 * k];
            xlv[k] = v;
            float t = v + xrv[k];
            t = t > 0.f ? t : 0.2f * t;
            float pe = t * attv[k];
            if (k < 2) p0 += pe; else if (k < 4) p1 += pe; else p2 += pe;
        }
#pragma unroll
        for (int o = 16; o; o >>= 1) {
            p0 += __shfl_xor_sync(0xffffffffu, p0, o);
            p1 += __shfl_xor_sync(0xffffffffu, p1, o);
            p2 += __shfl_xor_sync(0xffffffffu, p2, o);
        }
        float s0, w0, s1, w1, s2, w2;
        if (p0 > m0) { s0 = __expf(m0 - p0); m0 = p0; d0 = d0 * s0 + 1.f; w0 = 1.f; }
        else         { w0 = __expf(p0 - m0); d0 += w0; s0 = 1.f; }
        if (p1 > m1) { s1 = __expf(m1 - p1); m1 = p1; d1 = d1 * s1 + 1.f; w1 = 1.f; }
        else         { w1 = __expf(p1 - m1); d1 += w1; s1 = 1.f; }
        if (p2 > m2) { s2 = __expf(m2 - p2); m2 = p2; d2 = d2 * s2 + 1.f; w2 = 1.f; }
        else         { w2 = __expf(p2 - m2); d2 += w2; s2 = 1.f; }
        acc[0] = acc[0] * s0 + w0 * xlv[0];
        acc[1] = acc[1] * s0 + w0 * xlv[1];
        acc[2] = acc[2] * s1 + w1 * xlv[2];
        acc[3] = acc[3] * s1 + w1 * xlv[3];
        acc[4] = acc[4] * s2 + w2 * xlv[4];
        acc[5] = acc[5] * s2 + w2 * xlv[5];
    }
    float i0 = 1.f / d0, i1 = 1.f / d1, i2 = 1.f / d2;
#pragma unroll
    for (int k = 0; k < 6; k++) {
        float inv = (k < 2) ? i0 : (k < 4) ? i1 : i2;
        int c = lane + 32 * k;
        float o = acc[k] * inv + bias[c];
        out_fc[(size_t)i * FDIM + c] = o;
        out_pre[(size_t)i * FDIM + c] = o > 0.f ? o : 0.01f * o;
    }
}

// ---------------- pooling (batch is sorted int32 -> register accumulate) --
__global__ __launch_bounds__(192) void k_pool(
    const int* __restrict__ batch, const float* __restrict__ pre)
{
    const int NPB = 128;
    int n0 = blockIdx.x * NPB;
    int t = threadIdx.x;     // channel 0..191
    int nend = n0 + NPB; if (nend > N_NODES) nend = N_NODES;
    float a = 0.f; int cnt = 0; int cur = -1;
    for (int n = n0; n < nend; n++) {
        int g = __ldg(&batch[n]);
        if ((unsigned)g >= NUM_GRAPHS) continue;  // defensive
        if (g != cur) {
            if (cur >= 0) {
                atomicAdd(&g_gsum[cur * FDIM + t], a);
                if (t == 0) atomicAdd(&g_gcnt[cur], cnt);
            }
            a = 0.f; cnt = 0; cur = g;
        }
        a += pre[(size_t)n * FDIM + t];
        cnt++;
    }
    if (cur >= 0) {
        atomicAdd(&g_gsum[cur * FDIM + t], a);
        if (t == 0) atomicAdd(&g_gcnt[cur], cnt);
    }
}

// ---------------- post_pool + classifier ---------------------------------
__global__ __launch_bounds__(192) void k_final(
    const float* __restrict__ Wc, const float* __restrict__ bc,
    float* __restrict__ out_logits, float* __restrict__ out_post)
{
    int g = blockIdx.x;
    int t = threadIdx.x;
    __shared__ float sp[FDIM];
    float cnt = (float)g_gcnt[g];
    cnt = fmaxf(cnt, 1.f);
    float v = g_gsum[g * FDIM + t] / cnt;
    out_post[g * FDIM + t] = v;
    sp[t] = v;
    __syncthreads();
    if (t < NUM_CLASSES) {
        float s = bc[t];
        for (int k = 0; k < FDIM; k++) s += sp[k] * Wc[k * NUM_CLASSES + t];
        out_logits[g * NUM_CLASSES + t] = s;
    }
}

// ---------------- launch ----------------
extern "C" void kernel_launch(void* const* d_in, const int* in_sizes, int n_in,
                              void* d_out, int out_size)
{
    const float* x     = (const float*)d_in[0];
    const int*   eidx  = (const int*)d_in[1];    // int32 (jax x64 disabled)
    const int*   batch = (const int*)d_in[2];    // int32
    const float* Wl    = (const float*)d_in[3];
    const float* bl    = (const float*)d_in[4];
    const float* Wr    = (const float*)d_in[5];
    const float* br    = (const float*)d_in[6];
    const float* att   = (const float*)d_in[7];
    const float* bias  = (const float*)d_in[8];
    const float* Wc    = (const float*)d_in[9];
    const float* bc    = (const float*)d_in[10];
    float* out = (float*)d_out;

    int E = in_sizes[1] / 2;
    int ET = E + N_NODES;

    // output layout: (logits, pre_pool, post_pool, first_conv) flattened
    float* out_logits = out;
    float* out_pre    = out + NUM_GRAPHS * NUM_CLASSES;
    float* out_post   = out_pre + (size_t)N_NODES * FDIM;
    float* out_fc     = out_post + NUM_GRAPHS * FDIM;

    k_zero<<<(N_NODES + 255) / 256, 256>>>();
    k_gemm<<<dim3(3, (N_NODES + 127) / 128), 256>>>(x, Wl, Wr, bl, br);
    k_deg<<<(ET + 255) / 256, 256>>>(eidx, E, ET);
    int nblk = (N_NODES + 1023) / 1024;
    k_scan1<<<nblk, 1024>>>();
    k_scan2<<<1, 32>>>(nblk);
    k_scan3<<<(N_NODES + 255) / 256, 256>>>();
    k_fill<<<(ET + 255) / 256, 256>>>(eidx, E, ET);
    k_attn<<<(N_NODES * 32 + 255) / 256, 256>>>(att, bias, out_fc, out_pre);
    k_pool<<<(N_NODES + 127) / 128, 192>>>(batch, out_pre);
    k_final<<<NUM_GRAPHS, 192>>>(Wc, bc, out_logits, out_post);
}

// round 13
// speedup vs baseline: 1.4630x; 1.4630x over previous
#include <cuda_runtime.h>
#include <cuda_bf16.h>
#include <math.h>
#include <stdint.h>

#define N_NODES 100000
#define IN_DIM 256
#define HID 64
#define HEADS 3
#define FDIM 192          // HEADS*HID
#define NCOLS 384         // FDIM*2 (xl|xr)
#define NUM_CLASSES 10
#define NUM_GRAPHS 64
#define MAX_ET 1700000    // 1.6M edges + 100k self loops

// ---------------- static scratch (no allocations allowed) ----------------
__device__ float g_xl[(size_t)N_NODES * FDIM];
__device__ float g_xr[(size_t)N_NODES * FDIM];
__device__ __nv_bfloat16 g_wt_hi[NCOLS * IN_DIM];   // transposed W: [n][k]
__device__ __nv_bfloat16 g_wt_lo[NCOLS * IN_DIM];
__device__ int   g_src[MAX_ET];
__device__ int   g_deg[N_NODES];
__device__ int   g_tmp[N_NODES];
__device__ int   g_off[N_NODES + 1];
__device__ int   g_cur[N_NODES];
__device__ int   g_bsum[128];
__device__ float g_gsum[NUM_GRAPHS * FDIM];
__device__ int   g_gcnt[NUM_GRAPHS];

// ---------------- init ----------------
__global__ void k_zero() {
    int i = blockIdx.x * blockDim.x + threadIdx.x;
    if (i < N_NODES) g_deg[i] = 0;
    if (i < NUM_GRAPHS * FDIM) g_gsum[i] = 0.f;
    if (i < NUM_GRAPHS) g_gcnt[i] = 0;
}

// ---------------- W transpose + bf16 hi/lo split --------------------------
__global__ void k_wsplit(const float* __restrict__ Wl, const float* __restrict__ Wr) {
    int i = blockIdx.x * blockDim.x + threadIdx.x;   // i = n*256 + k
    if (i >= NCOLS * IN_DIM) return;
    int n = i >> 8, k = i & 255;
    float w = (n < FDIM) ? Wl[k * FDIM + n] : Wr[k * FDIM + (n - FDIM)];
    __nv_bfloat16 hi = __float2bfloat16(w);
    __nv_bfloat16 lo = __float2bfloat16(w - __bfloat162float(hi));
    g_wt_hi[i] = hi;
    g_wt_lo[i] = lo;
}

// ---------------- HMMA helper: m16n8k16 bf16 (baseline PTX, no 'a' gate) --
__device__ __forceinline__ void mma16816(float* c, const uint32_t* a,
                                         uint32_t b0, uint32_t b1) {
    asm volatile(
        "mma.sync.aligned.m16n8k16.row.col.f32.bf16.bf16.f32 "
        "{%0,%1,%2,%3}, {%4,%5,%6,%7}, {%8,%9}, {%0,%1,%2,%3};"
        : "+f"(c[0]), "+f"(c[1]), "+f"(c[2]), "+f"(c[3])
        : "r"(a[0]), "r"(a[1]), "r"(a[2]), "r"(a[3]), "r"(b0), "r"(b1));
}

// ---------------- mma.sync GEMM: [xl|xr] = x @ [W_l|W_r] + bias -----------
// CTA 128x128, K-chunks 32, 8 warps (4x2), warp tile 32x64.
// bf16x3 split: hi*hi + hi*lo + lo*hi, fp32 accumulate.
#define SMSTR 36   // smem row stride in bf16 (32 + 4 pad)
__global__ __launch_bounds__(256) void k_gemm_mma(
    const float* __restrict__ x,
    const float* __restrict__ bl, const float* __restrict__ br)
{
    __shared__ __nv_bfloat16 Ah[128 * SMSTR], Al[128 * SMSTR];
    __shared__ __nv_bfloat16 Bh[128 * SMSTR], Bl[128 * SMSTR];
    const int tid = threadIdx.x;
    const int wid = tid >> 5, lane = tid & 31;
    const int g = lane >> 2, tig = lane & 3;   // groupID, thread-in-group
    const int wm = wid & 3, wn = wid >> 2;     // warp grid 4x2
    const int row0 = blockIdx.y * 128, n0 = blockIdx.x * 128;

    float acc[2][8][4];
#pragma unroll
    for (int mi = 0; mi < 2; mi++)
#pragma unroll
        for (int ni = 0; ni < 8; ni++)
#pragma unroll
            for (int q = 0; q < 4; q++) acc[mi][ni][q] = 0.f;

    for (int kc = 0; kc < IN_DIM; kc += 32) {
        __syncthreads();
        // ---- A tile: x[row0..+127][kc..+31] fp32 -> hi/lo bf16 in smem
#pragma unroll
        for (int it = 0; it < 4; it++) {
            int idx = it * 256 + tid;          // 1024 float4 slots
            int row = idx >> 3, c4 = (idx & 7) * 4;
            float4 v = make_float4(0.f, 0.f, 0.f, 0.f);
            int gr = row0 + row;
            if (gr < N_NODES) v = *(const float4*)&x[(size_t)gr * IN_DIM + kc + c4];
            float vv[4] = {v.x, v.y, v.z, v.w};
            __nv_bfloat16 h[4], l[4];
#pragma unroll
            for (int q = 0; q < 4; q++) {
                h[q] = __float2bfloat16(vv[q]);
                l[q] = __float2bfloat16(vv[q] - __bfloat162float(h[q]));
            }
            *(uint2*)&Ah[row * SMSTR + c4] = *(uint2*)h;
            *(uint2*)&Al[row * SMSTR + c4] = *(uint2*)l;
        }
        // ---- B tile: Wt[n0..+127][kc..+31] bf16 hi/lo
#pragma unroll
        for (int it = 0; it < 4; it++) {
            int idx = it * 256 + tid;
            int row = idx >> 3, c4 = (idx & 7) * 4;
            size_t gs = (size_t)(n0 + row) * IN_DIM + kc + c4;
            *(uint2*)&Bh[row * SMSTR + c4] = *(const uint2*)&g_wt_hi[gs];
            *(uint2*)&Bl[row * SMSTR + c4] = *(const uint2*)&g_wt_lo[gs];
        }
        __syncthreads();

#pragma unroll
        for (int ks = 0; ks < 2; ks++) {
            const int ko = ks * 16;
            uint32_t ah[2][4], al[2][4];
#pragma unroll
            for (int mi = 0; mi < 2; mi++) {
                int r0 = wm * 32 + mi * 16;
                int cA = ko + tig * 2;
                ah[mi][0] = *(const uint32_t*)&Ah[(r0 + g) * SMSTR + cA];
                ah[mi][1] = *(const uint32_t*)&Ah[(r0 + g + 8) * SMSTR + cA];
                ah[mi][2] = *(const uint32_t*)&Ah[(r0 + g) * SMSTR + cA + 8];
                ah[mi][3] = *(const uint32_t*)&Ah[(r0 + g + 8) * SMSTR + cA + 8];
                al[mi][0] = *(const uint32_t*)&Al[(r0 + g) * SMSTR + cA];
                al[mi][1] = *(const uint32_t*)&Al[(r0 + g + 8) * SMSTR + cA];
                al[mi][2] = *(const uint32_t*)&Al[(r0 + g) * SMSTR + cA + 8];
                al[mi][3] = *(const uint32_t*)&Al[(r0 + g + 8) * SMSTR + cA + 8];
            }
#pragma unroll
            for (int ni = 0; ni < 8; ni++) {
                int bnr = wn * 64 + ni * 8 + g;
                int cB = ko + tig * 2;
                uint32_t bh0 = *(const uint32_t*)&Bh[bnr * SMSTR + cB];
                uint32_t bh1 = *(const uint32_t*)&Bh[bnr * SMSTR + cB + 8];
                uint32_t bL0 = *(const uint32_t*)&Bl[bnr * SMSTR + cB];
                uint32_t bL1 = *(const uint32_t*)&Bl[bnr * SMSTR + cB + 8];
#pragma unroll
                for (int mi = 0; mi < 2; mi++) {
                    mma16816(acc[mi][ni], ah[mi], bh0, bh1);
                    mma16816(acc[mi][ni], ah[mi], bL0, bL1);
                    mma16816(acc[mi][ni], al[mi], bh0, bh1);
                }
            }
        }
    }

    // ---- epilogue: bias add + split store into g_xl / g_xr
#pragma unroll
    for (int mi = 0; mi < 2; mi++) {
#pragma unroll
        for (int half = 0; half < 2; half++) {
            int r = row0 + wm * 32 + mi * 16 + g + half * 8;
            if (r >= N_NODES) continue;
#pragma unroll
            for (int ni = 0; ni < 8; ni++) {
                int gc = n0 + wn * 64 + ni * 8 + tig * 2;
                float v0 = acc[mi][ni][half * 2 + 0];
                float v1 = acc[mi][ni][half * 2 + 1];
                if (gc < FDIM) {
                    float2 o = make_float2(v0 + bl[gc], v1 + bl[gc + 1]);
                    *(float2*)&g_xl[(size_t)r * FDIM + gc] = o;
                } else {
                    int c = gc - FDIM;
                    float2 o = make_float2(v0 + br[c], v1 + br[c + 1]);
                    *(float2*)&g_xr[(size_t)r * FDIM + c] = o;
                }
            }
        }
    }
}

// ---------------- CSR build (edge_index is INT32) -------------------------
__global__ void k_deg(const int* __restrict__ eidx, int E, int ET) {
    int e = blockIdx.x * blockDim.x + threadIdx.x;
    if (e >= ET) return;
    int dst = (e < E) ? eidx[(size_t)E + e] : (e - E);
    if ((unsigned)dst >= N_NODES) return;
    atomicAdd(&g_deg[dst], 1);
}

__global__ void k_scan1() {
    __shared__ int s[1024];
    int tid = threadIdx.x;
    int i = blockIdx.x * 1024 + tid;
    int v = (i < N_NODES) ? g_deg[i] : 0;
    s[tid] = v;
    __syncthreads();
#pragma unroll
    for (int o = 1; o < 1024; o <<= 1) {
        int t = (tid >= o) ? s[tid - o] : 0;
        __syncthreads();
        s[tid] += t;
        __syncthreads();
    }
    if (i < N_NODES) g_tmp[i] = s[tid];
    if (tid == 1023) g_bsum[blockIdx.x] = s[1023];
}

__global__ void k_scan2(int nblk) {
    if (threadIdx.x == 0 && blockIdx.x == 0) {
        int run = 0;
        for (int b = 0; b < nblk; b++) { int t = g_bsum[b]; g_bsum[b] = run; run += t; }
    }
}

__global__ void k_scan3() {
    int i = blockIdx.x * blockDim.x + threadIdx.x;
    if (i >= N_NODES) return;
    int val = g_tmp[i] + g_bsum[i >> 10];
    g_off[i + 1] = val;
    g_cur[i] = val - g_deg[i];
    if (i == 0) g_off[0] = 0;
}

__global__ void k_fill(const int* __restrict__ eidx, int E, int ET) {
    int e = blockIdx.x * blockDim.x + threadIdx.x;
    if (e >= ET) return;
    int src, dst;
    if (e < E) { src = eidx[e]; dst = eidx[(size_t)E + e]; }
    else       { src = e - E; dst = e - E; }
    if ((unsigned)dst >= N_NODES || (unsigned)src >= N_NODES) return;
    int p = atomicAdd(&g_cur[dst], 1);
    if ((unsigned)p < MAX_ET) g_src[p] = src;
}

// ---------------- warp-per-node GATv2 with online softmax ----------------
__global__ __launch_bounds__(256) void k_attn(
    const float* __restrict__ att, const float* __restrict__ bias,
    float* __restrict__ out_fc, float* __restrict__ out_pre)
{
    int warp = (blockIdx.x * blockDim.x + threadIdx.x) >> 5;
    int lane = threadIdx.x & 31;
    if (warp >= N_NODES) return;
    const int i = warp;

    float xrv[6], attv[6];
#pragma unroll
    for (int k = 0; k < 6; k++) {
        int c = lane + 32 * k;
        xrv[k] = g_xr[(size_t)i * FDIM + c];
        attv[k] = att[c];
    }
    int beg = g_off[i], end = g_off[i + 1];

    float m0 = -1e30f, m1 = -1e30f, m2 = -1e30f;
    float d0 = 0.f, d1 = 0.f, d2 = 0.f;
    float acc[6] = {0.f, 0.f, 0.f, 0.f, 0.f, 0.f};

    for (int e = beg; e < end; e++) {
        int s = g_src[e];
        const float* xl = &g_xl[(size_t)s * FDIM];
        float xlv[6];
        float p0 = 0.f, p1 = 0.f, p2 = 0.f;
#pragma unroll
        for (int k = 0; k < 6; k++) {
            float v = xl[lane + 32 * k];
            xlv[k] = v;
            float t = v + xrv[k];
            t = t > 0.f ? t : 0.2f * t;
            float pe = t * attv[k];
            if (k < 2) p0 += pe; else if (k < 4) p1 += pe; else p2 += pe;
        }
#pragma unroll
        for (int o = 16; o; o >>= 1) {
            p0 += __shfl_xor_sync(0xffffffffu, p0, o);
            p1 += __shfl_xor_sync(0xffffffffu, p1, o);
            p2 += __shfl_xor_sync(0xffffffffu, p2, o);
        }
        float s0, w0, s1, w1, s2, w2;
        if (p0 > m0) { s0 = __expf(m0 - p0); m0 = p0; d0 = d0 * s0 + 1.f; w0 = 1.f; }
        else         { w0 = __expf(p0 - m0); d0 += w0; s0 = 1.f; }
        if (p1 > m1) { s1 = __expf(m1 - p1); m1 = p1; d1 = d1 * s1 + 1.f; w1 = 1.f; }
        else         { w1 = __expf(p1 - m1); d1 += w1; s1 = 1.f; }
        if (p2 > m2) { s2 = __expf(m2 - p2); m2 = p2; d2 = d2 * s2 + 1.f; w2 = 1.f; }
        else         { w2 = __expf(p2 - m2); d2 += w2; s2 = 1.f; }
        acc[0] = acc[0] * s0 + w0 * xlv[0];
        acc[1] = acc[1] * s0 + w0 * xlv[1];
        acc[2] = acc[2] * s1 + w1 * xlv[2];
        acc[3] = acc[3] * s1 + w1 * xlv[3];
        acc[4] = acc[4] * s2 + w2 * xlv[4];
        acc[5] = acc[5] * s2 + w2 * xlv[5];
    }
    float i0 = 1.f / d0, i1 = 1.f / d1, i2 = 1.f / d2;
#pragma unroll
    for (int k = 0; k < 6; k++) {
        float inv = (k < 2) ? i0 : (k < 4) ? i1 : i2;
        int c = lane + 32 * k;
        float o = acc[k] * inv + bias[c];
        out_fc[(size_t)i * FDIM + c] = o;
        out_pre[(size_t)i * FDIM + c] = o > 0.f ? o : 0.01f * o;
    }
}

// ---------------- pooling (batch sorted int32) ----------------------------
__global__ __launch_bounds__(192) void k_pool(
    const int* __restrict__ batch, const float* __restrict__ pre)
{
    const int NPB = 128;
    int n0 = blockIdx.x * NPB;
    int t = threadIdx.x;
    int nend = n0 + NPB; if (nend > N_NODES) nend = N_NODES;
    float a = 0.f; int cnt = 0; int cur = -1;
    for (int n = n0; n < nend; n++) {
        int g = __ldg(&batch[n]);
        if ((unsigned)g >= NUM_GRAPHS) continue;
        if (g != cur) {
            if (cur >= 0) {
                atomicAdd(&g_gsum[cur * FDIM + t], a);
                if (t == 0) atomicAdd(&g_gcnt[cur], cnt);
            }
            a = 0.f; cnt = 0; cur = g;
        }
        a += pre[(size_t)n * FDIM + t];
        cnt++;
    }
    if (cur >= 0) {
        atomicAdd(&g_gsum[cur * FDIM + t], a);
        if (t == 0) atomicAdd(&g_gcnt[cur], cnt);
    }
}

// ---------------- post_pool + classifier ---------------------------------
__global__ __launch_bounds__(192) void k_final(
    const float* __restrict__ Wc, const float* __restrict__ bc,
    float* __restrict__ out_logits, float* __restrict__ out_post)
{
    int g = blockIdx.x;
    int t = threadIdx.x;
    __shared__ float sp[FDIM];
    float cnt = (float)g_gcnt[g];
    cnt = fmaxf(cnt, 1.f);
    float v = g_gsum[g * FDIM + t] / cnt;
    out_post[g * FDIM + t] = v;
    sp[t] = v;
    __syncthreads();
    if (t < NUM_CLASSES) {
        float s = bc[t];
        for (int k = 0; k < FDIM; k++) s += sp[k] * Wc[k * NUM_CLASSES + t];
        out_logits[g * NUM_CLASSES + t] = s;
    }
}

// ---------------- launch ----------------
extern "C" void kernel_launch(void* const* d_in, const int* in_sizes, int n_in,
                              void* d_out, int out_size)
{
    const float* x     = (const float*)d_in[0];
    const int*   eidx  = (const int*)d_in[1];
    const int*   batch = (const int*)d_in[2];
    const float* Wl    = (const float*)d_in[3];
    const float* bl    = (const float*)d_in[4];
    const float* Wr    = (const float*)d_in[5];
    const float* br    = (const float*)d_in[6];
    const float* att   = (const float*)d_in[7];
    const float* bias  = (const float*)d_in[8];
    const float* Wc    = (const float*)d_in[9];
    const float* bc    = (const float*)d_in[10];
    float* out = (float*)d_out;

    int E = in_sizes[1] / 2;
    int ET = E + N_NODES;

    float* out_logits = out;
    float* out_pre    = out + NUM_GRAPHS * NUM_CLASSES;
    float* out_post   = out_pre + (size_t)N_NODES * FDIM;
    float* out_fc     = out_post + NUM_GRAPHS * FDIM;

    k_zero<<<(N_NODES + 255) / 256, 256>>>();
    k_wsplit<<<(NCOLS * IN_DIM + 255) / 256, 256>>>(Wl, Wr);
    k_gemm_mma<<<dim3(3, (N_NODES + 127) / 128), 256>>>(x, bl, br);
    k_deg<<<(ET + 255) / 256, 256>>>(eidx, E, ET);
    int nblk = (N_NODES + 1023) / 1024;
    k_scan1<<<nblk, 1024>>>();
    k_scan2<<<1, 32>>>(nblk);
    k_scan3<<<(N_NODES + 255) / 256, 256>>>();
    k_fill<<<(ET + 255) / 256, 256>>>(eidx, E, ET);
    k_attn<<<(N_NODES * 32 + 255) / 256, 256>>>(att, bias, out_fc, out_pre);
    k_pool<<<(N_NODES + 127) / 128, 192>>>(batch, out_pre);
    k_final<<<NUM_GRAPHS, 192>>>(Wc, bc, out_logits, out_post);
}